// round 12
// baseline (speedup 1.0000x reference)
#include <cuda_runtime.h>
#include <cuda_bf16.h>
#include <cstdint>

#define NUSR 100000
#define NTXN 400000
#define NEDG 400000
#define HDIM 128
#define NLAY 3
#define HID2 64
#define OUTD 2
#define EPSV 1e-5f
#define NTOT (NUSR + NTXN)

// ===================== helpers =====================
__device__ __forceinline__ uint32_t smem_to_u32(const void* p) {
    uint32_t a;
    asm("{ .reg .u64 t; cvta.to.shared.u64 t, %1; cvt.u32.u64 %0, t; }" : "=r"(a) : "l"(p));
    return a;
}
__device__ __forceinline__ void split2(float x, float y, uint32_t& hi, uint32_t& lo) {
    __nv_bfloat162 h = __floats2bfloat162_rn(x, y);
    float rx = x - __bfloat162float(h.x);
    float ry = y - __bfloat162float(h.y);
    __nv_bfloat162 l = __floats2bfloat162_rn(rx, ry);
    hi = *(uint32_t*)&h;
    lo = *(uint32_t*)&l;
}
__device__ __forceinline__ float2 lds2(uint32_t addr) {
    float2 v;
    asm volatile("ld.shared.v2.f32 {%0,%1}, [%2];" : "=f"(v.x), "=f"(v.y) : "r"(addr));
    return v;
}
__device__ __forceinline__ void sts4(uint32_t addr, float4 v) {
    asm volatile("st.shared.v4.f32 [%0], {%1,%2,%3,%4};"
                 :: "r"(addr), "f"(v.x), "f"(v.y), "f"(v.z), "f"(v.w));
}
#define LDSM_X4(r0, r1, r2, r3, addr) \
    asm volatile("ldmatrix.sync.aligned.m8n8.x4.shared.b16 {%0,%1,%2,%3}, [%4];" \
                 : "=r"(r0), "=r"(r1), "=r"(r2), "=r"(r3) : "r"(addr))
#define MMA_BF16(d, a, b0, b1) \
    asm volatile("mma.sync.aligned.m16n8k16.row.col.f32.bf16.bf16.f32 " \
                 "{%0,%1,%2,%3}, {%4,%5,%6,%7}, {%8,%9}, {%0,%1,%2,%3};" \
                 : "+f"((d)[0]), "+f"((d)[1]), "+f"((d)[2]), "+f"((d)[3]) \
                 : "r"((a)[0]), "r"((a)[1]), "r"((a)[2]), "r"((a)[3]), "r"(b0), "r"(b1))

// ===================== scratch (device globals) =====================
__device__ float g_hu0[(size_t)NUSR * HDIM];
__device__ float g_hu1[(size_t)NUSR * HDIM];
__device__ float g_ht0[(size_t)NTXN * HDIM];
__device__ float g_ht1[(size_t)NTXN * HDIM];
__device__ int   g_cntu[NUSR];
__device__ int   g_cntt[NTXN];
__device__ int   g_startu[NUSR];
__device__ int   g_startt[NTXN];
__device__ int   g_tmpu[NUSR];
__device__ int   g_tmpt[NTXN];
__device__ int   g_permu[NEDG];
__device__ int   g_permt[NEDG];
__device__ int   g_cursor[2];
__device__ float4 g_wimg[6 * 2 * 4096];   // [6 (l,t)] x (hi 64KB + lo 64KB)
__device__ float4 g_w1img[2048];          // W1 hi 16KB + lo 16KB

// ===================== CSR build kernels =====================
__global__ void zero_i(int* __restrict__ p, int n) {
    int i = blockIdx.x * blockDim.x + threadIdx.x;
    if (i < n) p[i] = 0;
}

__global__ void count_deg(const int* __restrict__ dst, int* __restrict__ cnt, int n) {
    int i = blockIdx.x * blockDim.x + threadIdx.x;
    if (i < n) atomicAdd(&cnt[__ldg(dst + i)], 1);
}

__global__ void assign_off(const int* __restrict__ cnt, int* __restrict__ start,
                           int* __restrict__ tmp, int* cursor, int n) {
    __shared__ int wsum[8];
    __shared__ int sbase;
    int i = blockIdx.x * 256 + threadIdx.x;
    int lane = threadIdx.x & 31, w = threadIdx.x >> 5;
    int c = (i < n) ? __ldg(cnt + i) : 0;
    int pre = c;
    #pragma unroll
    for (int o = 1; o < 32; o <<= 1) {
        int u = __shfl_up_sync(0xffffffffu, pre, o);
        if (lane >= o) pre += u;
    }
    if (lane == 31) wsum[w] = pre;
    __syncthreads();
    if (threadIdx.x == 0) {
        int s = 0;
        #pragma unroll
        for (int j = 0; j < 8; j++) { int t = wsum[j]; wsum[j] = s; s += t; }
        sbase = atomicAdd(cursor, s);
    }
    __syncthreads();
    int off = sbase + wsum[w] + pre - c;
    if (i < n) { start[i] = off; tmp[i] = off; }
}

__global__ void fill_perm(const int* __restrict__ src, const int* __restrict__ dst,
                          int* __restrict__ tmp, int* __restrict__ perm, int n) {
    int i = blockIdx.x * blockDim.x + threadIdx.x;
    if (i < n) {
        int d = __ldg(dst + i);
        int slot = atomicAdd(&tmp[d], 1);
        perm[slot] = __ldg(src + i);
    }
}

// ===================== weight prep =====================
__global__ void wprep(const float* __restrict__ Wl, const float* __restrict__ Wr) {
    int lt = blockIdx.x;
    const float* wl = Wl + (size_t)lt * HDIM * HDIM;
    const float* wr = Wr + (size_t)lt * HDIM * HDIM;
    unsigned char* dhi = (unsigned char*)g_wimg + (size_t)lt * 131072;
    unsigned char* dlo = dhi + 65536;
    for (int e = threadIdx.x; e < 256 * 128; e += blockDim.x) {
        int k = e >> 7, n = e & 127;
        float v = (k < 128) ? __ldg(wl + k * HDIM + n) : __ldg(wr + (k - 128) * HDIM + n);
        __nv_bfloat16 hi = __float2bfloat16_rn(v);
        __nv_bfloat16 lo = __float2bfloat16_rn(v - __bfloat162float(hi));
        uint32_t off = (uint32_t)n * 512 + (((uint32_t)k * 2) ^ (uint32_t)((n & 7) * 16));
        *(__nv_bfloat16*)(dhi + off) = hi;
        *(__nv_bfloat16*)(dlo + off) = lo;
    }
}
__global__ void w1prep(const float* __restrict__ W1) {
    unsigned char* dhi = (unsigned char*)g_w1img;
    unsigned char* dlo = dhi + 16384;
    for (int e = blockIdx.x * blockDim.x + threadIdx.x; e < 128 * 64; e += gridDim.x * blockDim.x) {
        int k = e >> 6, n = e & 63;
        float v = __ldg(W1 + k * HID2 + n);
        __nv_bfloat16 hi = __float2bfloat16_rn(v);
        __nv_bfloat16 lo = __float2bfloat16_rn(v - __bfloat162float(hi));
        uint32_t off = (uint32_t)n * 256 + (((uint32_t)k * 2) ^ (uint32_t)((n & 7) * 16));
        *(__nv_bfloat16*)(dhi + off) = hi;
        *(__nv_bfloat16*)(dlo + off) = lo;
    }
}

// ===================== fused SAGE layer: CSR-mean + dual GEMM + bias + BN + ReLU =====================
// out[m,:] = relu(BN( mean_{p in N(m)} srcfeat[srcidx?x[p]:p, :] @ Wl
//                     + self[selfidx?x[m]:m, :] @ Wr + bias ))
// CTA = 128 rows; staging: warp w gathers rows w*16..w*16+15 into swizzled smem A-tile.
#define SMB_SCL  0
#define SMB_SFT  512
#define SMB_A1   1024
#define SMB_BHI  (1024 + 65536)
#define SMB_BLO  (SMB_BHI + 65536)
#define SMB_TOT  (SMB_BLO + 65536)

__global__ __launch_bounds__(256, 1) void gemm_sage(
    const int* __restrict__ start, const int* __restrict__ cnt, const int* __restrict__ perm,
    const float* __restrict__ srcfeat, const int* __restrict__ srcidx,
    const float* __restrict__ self,    const int* __restrict__ selfidx,
    const float4* __restrict__ wimg,
    const float* __restrict__ bias,
    const float* __restrict__ gma, const float* __restrict__ bta,
    const float* __restrict__ mu,  const float* __restrict__ var,
    float* __restrict__ out, int M)
{
    extern __shared__ char smem[];
    uint32_t sb = smem_to_u32(smem);
    const int tid  = threadIdx.x;
    const int lane = tid & 31;
    const int wid  = tid >> 5;
    const int row0 = blockIdx.x * 128;

    // ---- weights -> smem ----
    {
        float4* bs = (float4*)(smem + SMB_BHI);
        #pragma unroll 4
        for (int i = tid; i < 8192; i += 256) bs[i] = __ldg(wimg + i);
    }
    // ---- BN/bias consts ----
    if (tid < HDIM) {
        float rs = rsqrtf(__ldg(var + tid) + EPSV) * __ldg(gma + tid);
        ((float*)(smem + SMB_SCL))[tid] = rs;
        ((float*)(smem + SMB_SFT))[tid] = __ldg(bta + tid) + (__ldg(bias + tid) - __ldg(mu + tid)) * rs;
    }

    // ---- staging: CSR gather-mean into swizzled smem A1 tile ----
    {
        const float4* sf = (const float4*)srcfeat;
        const uint32_t sA = sb + SMB_A1;
        for (int lr = wid * 16; lr < wid * 16 + 16; lr++) {
            int grow = row0 + lr;
            float4 acc = make_float4(0.f, 0.f, 0.f, 0.f);
            if (grow < M) {
                int s = __ldg(start + grow);
                int c = __ldg(cnt + grow);
                int j = 0;
                for (; j + 2 <= c; j += 2) {
                    int p0 = __ldg(perm + s + j);
                    int p1 = __ldg(perm + s + j + 1);
                    if (srcidx) { p0 = __ldg(srcidx + p0); p1 = __ldg(srcidx + p1); }
                    float4 v0 = __ldg(sf + (size_t)p0 * 32 + lane);
                    float4 v1 = __ldg(sf + (size_t)p1 * 32 + lane);
                    acc.x += v0.x + v1.x; acc.y += v0.y + v1.y;
                    acc.z += v0.z + v1.z; acc.w += v0.w + v1.w;
                }
                if (j < c) {
                    int p0 = __ldg(perm + s + j);
                    if (srcidx) p0 = __ldg(srcidx + p0);
                    float4 v0 = __ldg(sf + (size_t)p0 * 32 + lane);
                    acc.x += v0.x; acc.y += v0.y; acc.z += v0.z; acc.w += v0.w;
                }
                float scn = 1.f / (float)(c > 1 ? c : 1);
                acc.x *= scn; acc.y *= scn; acc.z *= scn; acc.w *= scn;
            }
            sts4(sA + (uint32_t)lr * 512 + (((uint32_t)lane * 16) ^ (uint32_t)((lr & 7) << 4)), acc);
        }
    }
    __syncthreads();

    const int warp_m = wid & 3;
    const int warp_n = wid >> 2;
    const int m0 = row0 + warp_m * 32;
    const int n0 = warp_n * 64;
    const int g  = lane >> 2;
    const int tg = lane & 3;

    // self (A2) row pointers via optional index translation (clamped, stores guarded)
    const float* pa2[4];
    int rows[4] = { m0 + g, m0 + g + 8, m0 + g + 16, m0 + g + 24 };
    #pragma unroll
    for (int i = 0; i < 4; i++) {
        int r = rows[i] < M ? rows[i] : (M - 1);
        int sr = selfidx ? __ldg(selfidx + r) : r;
        pa2[i] = self + (size_t)sr * HDIM;
    }

    // B ldmatrix addresses
    const int n_off  = (lane & 7) + ((lane >> 4) << 3);
    const int k_half = (lane & 8) << 1;
    const uint32_t xorv = (uint32_t)((n_off & 7) << 4);
    uint32_t brow_hi[4], brow_lo[4];
    #pragma unroll
    for (int np = 0; np < 4; np++) {
        uint32_t nrow = (uint32_t)(n0 + np * 16 + n_off) * 512u;
        brow_hi[np] = sb + SMB_BHI + nrow;
        brow_lo[np] = sb + SMB_BLO + nrow;
    }

    // A1 smem read bases (local rows), xor-swizzled
    const uint32_t sA = sb + SMB_A1;
    uint32_t arow[4];
    #pragma unroll
    for (int i = 0; i < 4; i++) {
        uint32_t lr = (uint32_t)(warp_m * 32 + g + i * 8);
        arow[i] = sA + lr * 512;
    }
    const uint32_t axor = (uint32_t)(g << 4);

    float acc[2][8][4];
    #pragma unroll
    for (int mt = 0; mt < 2; mt++)
        #pragma unroll
        for (int nt = 0; nt < 8; nt++)
            #pragma unroll
            for (int q = 0; q < 4; q++) acc[mt][nt][q] = 0.f;

    #pragma unroll 2
    for (int kk = 0; kk < 16; kk++) {
        float2 x[4][2];
        if (kk < 8) {
            uint32_t b0 = (uint32_t)(kk * 64 + tg * 8);
            #pragma unroll
            for (int i = 0; i < 4; i++) {
                x[i][0] = lds2(arow[i] + (b0 ^ axor));
                x[i][1] = lds2(arow[i] + ((b0 + 32) ^ axor));
            }
        } else {
            int k0 = (kk - 8) * 16 + tg * 2;
            #pragma unroll
            for (int i = 0; i < 4; i++) {
                x[i][0] = *(const float2*)(pa2[i] + k0);
                x[i][1] = *(const float2*)(pa2[i] + k0 + 8);
            }
        }
        uint32_t ah[2][4], al[2][4];
        #pragma unroll
        for (int mt = 0; mt < 2; mt++) {
            int i0 = mt * 2, i1 = mt * 2 + 1;
            split2(x[i0][0].x, x[i0][0].y, ah[mt][0], al[mt][0]);
            split2(x[i1][0].x, x[i1][0].y, ah[mt][1], al[mt][1]);
            split2(x[i0][1].x, x[i0][1].y, ah[mt][2], al[mt][2]);
            split2(x[i1][1].x, x[i1][1].y, ah[mt][3], al[mt][3]);
        }

        uint32_t kterm = (uint32_t)((kk * 32 + k_half)) ^ xorv;
        #pragma unroll
        for (int np = 0; np < 4; np++) {
            uint32_t bh0, bh1, bh2, bh3, bl0, bl1, bl2, bl3;
            LDSM_X4(bh0, bh1, bh2, bh3, brow_hi[np] + kterm);
            LDSM_X4(bl0, bl1, bl2, bl3, brow_lo[np] + kterm);
            #pragma unroll
            for (int mt = 0; mt < 2; mt++) {
                MMA_BF16(acc[mt][2 * np],     ah[mt], bh0, bh1);
                MMA_BF16(acc[mt][2 * np],     al[mt], bh0, bh1);
                MMA_BF16(acc[mt][2 * np],     ah[mt], bl0, bl1);
                MMA_BF16(acc[mt][2 * np + 1], ah[mt], bh2, bh3);
                MMA_BF16(acc[mt][2 * np + 1], al[mt], bh2, bh3);
                MMA_BF16(acc[mt][2 * np + 1], ah[mt], bl2, bl3);
            }
        }
    }

    // ---- epilogue (out buffers are distinct from inputs; no pre-store sync needed) ----
    const float* scl = (const float*)(smem + SMB_SCL);
    const float* sft = (const float*)(smem + SMB_SFT);
    #pragma unroll
    for (int mt = 0; mt < 2; mt++) {
        int r_lo = m0 + mt * 16 + g;
        int r_hi = r_lo + 8;
        #pragma unroll
        for (int nt = 0; nt < 8; nt++) {
            int c = n0 + nt * 8 + tg * 2;
            float s0 = scl[c], s1 = scl[c + 1];
            float f0 = sft[c], f1 = sft[c + 1];
            if (r_lo < M) {
                float2 o;
                o.x = fmaxf(fmaf(acc[mt][nt][0], s0, f0), 0.f);
                o.y = fmaxf(fmaf(acc[mt][nt][1], s1, f1), 0.f);
                *(float2*)(out + (size_t)r_lo * HDIM + c) = o;
            }
            if (r_hi < M) {
                float2 o;
                o.x = fmaxf(fmaf(acc[mt][nt][2], s0, f0), 0.f);
                o.y = fmaxf(fmaf(acc[mt][nt][3], s1, f1), 0.f);
                *(float2*)(out + (size_t)r_hi * HDIM + c) = o;
            }
        }
    }
}

// ===================== tensor-core MLP head =====================
__global__ __launch_bounds__(256, 2) void mlp_mma(
    const float* __restrict__ hu, const float* __restrict__ ht,
    const float4* __restrict__ w1img,
    const float* __restrict__ b1, const float* __restrict__ W2, const float* __restrict__ b2,
    float* __restrict__ out)
{
    __shared__ float4 sB[2048];
    __shared__ float sb1[HID2];
    __shared__ float sW2[HID2 * OUTD];
    __shared__ float sb2[OUTD];
    for (int i = threadIdx.x; i < 2048; i += 256) sB[i] = __ldg(w1img + i);
    if (threadIdx.x < HID2) sb1[threadIdx.x] = __ldg(b1 + threadIdx.x);
    if (threadIdx.x < HID2 * OUTD) sW2[threadIdx.x] = __ldg(W2 + threadIdx.x);
    if (threadIdx.x < OUTD) sb2[threadIdx.x] = __ldg(b2 + threadIdx.x);
    __syncthreads();

    const int lane = threadIdx.x & 31;
    const int wid  = threadIdx.x >> 5;
    const int m0 = blockIdx.x * 256 + wid * 32;
    const int g  = lane >> 2;
    const int tg = lane & 3;

    const float* pa[4];
    int rows[4] = { m0 + g, m0 + g + 8, m0 + g + 16, m0 + g + 24 };
    #pragma unroll
    for (int i = 0; i < 4; i++) {
        int r = rows[i] < NTOT ? rows[i] : (NTOT - 1);
        pa[i] = (r < NUSR) ? hu + (size_t)r * HDIM : ht + (size_t)(r - NUSR) * HDIM;
    }

    const int n_off  = (lane & 7) + ((lane >> 4) << 3);
    const int k_half = (lane & 8) << 1;
    const uint32_t xorv = (uint32_t)((n_off & 7) << 4);
    uint32_t sbu = smem_to_u32(sB);
    uint32_t brow_hi[4], brow_lo[4];
    #pragma unroll
    for (int np = 0; np < 4; np++) {
        uint32_t nrow = (uint32_t)(np * 16 + n_off) * 256u;
        brow_hi[np] = sbu + nrow;
        brow_lo[np] = sbu + 16384u + nrow;
    }

    float acc[2][8][4];
    #pragma unroll
    for (int mt = 0; mt < 2; mt++)
        #pragma unroll
        for (int nt = 0; nt < 8; nt++)
            #pragma unroll
            for (int q = 0; q < 4; q++) acc[mt][nt][q] = 0.f;

    #pragma unroll 2
    for (int kk = 0; kk < 8; kk++) {
        int k0 = kk * 16 + tg * 2;
        float2 x[4][2];
        #pragma unroll
        for (int i = 0; i < 4; i++) {
            x[i][0] = *(const float2*)(pa[i] + k0);
            x[i][1] = *(const float2*)(pa[i] + k0 + 8);
        }
        uint32_t ah[2][4], al[2][4];
        #pragma unroll
        for (int mt = 0; mt < 2; mt++) {
            int i0 = mt * 2, i1 = mt * 2 + 1;
            split2(x[i0][0].x, x[i0][0].y, ah[mt][0], al[mt][0]);
            split2(x[i1][0].x, x[i1][0].y, ah[mt][1], al[mt][1]);
            split2(x[i0][1].x, x[i0][1].y, ah[mt][2], al[mt][2]);
            split2(x[i1][1].x, x[i1][1].y, ah[mt][3], al[mt][3]);
        }
        uint32_t kterm = (uint32_t)((kk * 32 + k_half)) ^ xorv;
        #pragma unroll
        for (int np = 0; np < 4; np++) {
            uint32_t bh0, bh1, bh2, bh3, bl0, bl1, bl2, bl3;
            LDSM_X4(bh0, bh1, bh2, bh3, brow_hi[np] + kterm);
            LDSM_X4(bl0, bl1, bl2, bl3, brow_lo[np] + kterm);
            #pragma unroll
            for (int mt = 0; mt < 2; mt++) {
                MMA_BF16(acc[mt][2 * np],     ah[mt], bh0, bh1);
                MMA_BF16(acc[mt][2 * np],     al[mt], bh0, bh1);
                MMA_BF16(acc[mt][2 * np],     ah[mt], bl0, bl1);
                MMA_BF16(acc[mt][2 * np + 1], ah[mt], bh2, bh3);
                MMA_BF16(acc[mt][2 * np + 1], al[mt], bh2, bh3);
                MMA_BF16(acc[mt][2 * np + 1], ah[mt], bl2, bl3);
            }
        }
    }

    #pragma unroll
    for (int mt = 0; mt < 2; mt++) {
        #pragma unroll
        for (int half = 0; half < 2; half++) {
            int row = m0 + mt * 16 + g + half * 8;
            float oA = 0.f, oB = 0.f;
            #pragma unroll
            for (int nt = 0; nt < 8; nt++) {
                int c = nt * 8 + tg * 2;
                float h0 = fmaxf(acc[mt][nt][half * 2 + 0] + sb1[c],     0.f);
                float h1 = fmaxf(acc[mt][nt][half * 2 + 1] + sb1[c + 1], 0.f);
                oA = fmaf(h0, sW2[c * OUTD],     fmaf(h1, sW2[(c + 1) * OUTD],     oA));
                oB = fmaf(h0, sW2[c * OUTD + 1], fmaf(h1, sW2[(c + 1) * OUTD + 1], oB));
            }
            oA += __shfl_xor_sync(0xffffffffu, oA, 1);
            oA += __shfl_xor_sync(0xffffffffu, oA, 2);
            oB += __shfl_xor_sync(0xffffffffu, oB, 1);
            oB += __shfl_xor_sync(0xffffffffu, oB, 2);
            if (tg == 0 && row < NTOT) {
                out[(size_t)row * OUTD + 0] = oA + sb2[0];
                out[(size_t)row * OUTD + 1] = oB + sb2[1];
            }
        }
    }
}

// ===================== launcher =====================
extern "C" void kernel_launch(void* const* d_in, const int* in_sizes, int n_in,
                              void* d_out, int out_size) {
    (void)in_sizes; (void)n_in; (void)out_size;
    const int*   x_user  = (const int*)  d_in[0];
    const int*   x_txn   = (const int*)  d_in[1];
    const int*   ei0_src = (const int*)  d_in[2];
    const int*   ei0_dst = (const int*)  d_in[3];
    const int*   ei1_src = (const int*)  d_in[4];
    const int*   ei1_dst = (const int*)  d_in[5];
    const float* emb_u   = (const float*)d_in[6];
    const float* emb_t   = (const float*)d_in[7];
    const float* Wl      = (const float*)d_in[8];
    const float* bl      = (const float*)d_in[9];
    const float* Wr      = (const float*)d_in[10];
    const float* bn_g    = (const float*)d_in[11];
    const float* bn_b    = (const float*)d_in[12];
    const float* bn_m    = (const float*)d_in[13];
    const float* bn_v    = (const float*)d_in[14];
    const float* W1      = (const float*)d_in[15];
    const float* b1      = (const float*)d_in[16];
    const float* W2      = (const float*)d_in[17];
    const float* b2      = (const float*)d_in[18];
    float* out = (float*)d_out;

    float *hu[2], *ht[2];
    int *cntu, *cntt, *startu, *startt, *tmpu, *tmpt, *permu, *permt, *cursor;
    float4 *wimg, *w1img;
    cudaGetSymbolAddress((void**)&hu[0],  g_hu0);
    cudaGetSymbolAddress((void**)&hu[1],  g_hu1);
    cudaGetSymbolAddress((void**)&ht[0],  g_ht0);
    cudaGetSymbolAddress((void**)&ht[1],  g_ht1);
    cudaGetSymbolAddress((void**)&cntu,   g_cntu);
    cudaGetSymbolAddress((void**)&cntt,   g_cntt);
    cudaGetSymbolAddress((void**)&startu, g_startu);
    cudaGetSymbolAddress((void**)&startt, g_startt);
    cudaGetSymbolAddress((void**)&tmpu,   g_tmpu);
    cudaGetSymbolAddress((void**)&tmpt,   g_tmpt);
    cudaGetSymbolAddress((void**)&permu,  g_permu);
    cudaGetSymbolAddress((void**)&permt,  g_permt);
    cudaGetSymbolAddress((void**)&cursor, g_cursor);
    cudaGetSymbolAddress((void**)&wimg,   g_wimg);
    cudaGetSymbolAddress((void**)&w1img,  g_w1img);

    cudaFuncSetAttribute(gemm_sage, cudaFuncAttributeMaxDynamicSharedMemorySize, SMB_TOT);

    // 0) bake weight images
    wprep<<<6, 256>>>(Wl, Wr);
    w1prep<<<8, 256>>>(W1);

    // 1) CSR build (layer-invariant)
    zero_i<<<(NTXN + 255) / 256, 256>>>(cntt, NTXN);
    zero_i<<<(NUSR + 255) / 256, 256>>>(cntu, NUSR);
    zero_i<<<1, 32>>>(cursor, 2);
    count_deg<<<(NEDG + 255) / 256, 256>>>(ei0_dst, cntt, NEDG);
    count_deg<<<(NEDG + 255) / 256, 256>>>(ei1_dst, cntu, NEDG);
    assign_off<<<(NTXN + 255) / 256, 256>>>(cntt, startt, tmpt, cursor + 0, NTXN);
    assign_off<<<(NUSR + 255) / 256, 256>>>(cntu, startu, tmpu, cursor + 1, NUSR);
    fill_perm<<<(NEDG + 255) / 256, 256>>>(ei0_src, ei0_dst, tmpt, permt, NEDG);
    fill_perm<<<(NEDG + 255) / 256, 256>>>(ei1_src, ei1_dst, tmpu, permu, NEDG);

    // 2) layers (double-buffered; layer 0 reads embeddings through index arrays)
    for (int l = 0; l < NLAY; l++) {
        const float* su  = (l == 0) ? emb_u : hu[(l + 1) & 1];   // user features source
        const float* st_ = (l == 0) ? emb_t : ht[(l + 1) & 1];   // txn features source
        const int* ixu = (l == 0) ? x_user : nullptr;
        const int* ixt = (l == 0) ? x_txn  : nullptr;
        float* out_t = ht[l & 1];
        float* out_u = hu[l & 1];

        // txn nodes: agg over user srcs; weights/bias (l,0), BN (l,1)
        {
            int lt = l * 2 + 0;
            gemm_sage<<<(NTXN + 127) / 128, 256, SMB_TOT>>>(
                startt, cntt, permt,
                su, ixu,            // src = user features
                st_, ixt,           // self = txn features
                wimg + (size_t)lt * 8192,
                bl   + (size_t)lt * HDIM,
                bn_g + (size_t)(l * 2 + 1) * HDIM, bn_b + (size_t)(l * 2 + 1) * HDIM,
                bn_m + (size_t)(l * 2 + 1) * HDIM, bn_v + (size_t)(l * 2 + 1) * HDIM,
                out_t, NTXN);
        }
        // user nodes: agg over txn srcs; weights/bias (l,1), BN (l,0)
        {
            int lt = l * 2 + 1;
            gemm_sage<<<(NUSR + 127) / 128, 256, SMB_TOT>>>(
                startu, cntu, permu,
                st_, ixt,           // src = txn features
                su, ixu,            // self = user features
                wimg + (size_t)lt * 8192,
                bl   + (size_t)lt * HDIM,
                bn_g + (size_t)(l * 2 + 0) * HDIM, bn_b + (size_t)(l * 2 + 0) * HDIM,
                bn_m + (size_t)(l * 2 + 0) * HDIM, bn_v + (size_t)(l * 2 + 0) * HDIM,
                out_u, NUSR);
        }
    }

    // 3) MLP head (final buffers: layer NLAY-1 wrote index (NLAY-1)&1 = 0)
    mlp_mma<<<(NTOT + 255) / 256, 256>>>(hu[(NLAY - 1) & 1], ht[(NLAY - 1) & 1],
                                         w1img, b1, W2, b2, out);
}

// round 13
// speedup vs baseline: 1.2397x; 1.2397x over previous
#include <cuda_runtime.h>
#include <cuda_bf16.h>
#include <cstdint>

#define NUSR 100000
#define NTXN 400000
#define NEDG 400000
#define HDIM 128
#define NLAY 3
#define HID2 64
#define OUTD 2
#define EPSV 1e-5f
#define NTOT (NUSR + NTXN)

// ===================== helpers =====================
__device__ __forceinline__ uint32_t smem_to_u32(const void* p) {
    uint32_t a;
    asm("{ .reg .u64 t; cvta.to.shared.u64 t, %1; cvt.u32.u64 %0, t; }" : "=r"(a) : "l"(p));
    return a;
}
__device__ __forceinline__ void split2(float x, float y, uint32_t& hi, uint32_t& lo) {
    __nv_bfloat162 h = __floats2bfloat162_rn(x, y);
    float rx = x - __bfloat162float(h.x);
    float ry = y - __bfloat162float(h.y);
    __nv_bfloat162 l = __floats2bfloat162_rn(rx, ry);
    hi = *(uint32_t*)&h;
    lo = *(uint32_t*)&l;
}
#define LDSM_X4(r0, r1, r2, r3, addr) \
    asm volatile("ldmatrix.sync.aligned.m8n8.x4.shared.b16 {%0,%1,%2,%3}, [%4];" \
                 : "=r"(r0), "=r"(r1), "=r"(r2), "=r"(r3) : "r"(addr))
#define MMA_BF16(d, a, b0, b1) \
    asm volatile("mma.sync.aligned.m16n8k16.row.col.f32.bf16.bf16.f32 " \
                 "{%0,%1,%2,%3}, {%4,%5,%6,%7}, {%8,%9}, {%0,%1,%2,%3};" \
                 : "+f"((d)[0]), "+f"((d)[1]), "+f"((d)[2]), "+f"((d)[3]) \
                 : "r"((a)[0]), "r"((a)[1]), "r"((a)[2]), "r"((a)[3]), "r"(b0), "r"(b1))

// ===================== scratch (device globals) =====================
__device__ float g_hu0[(size_t)NUSR * HDIM];
__device__ float g_hu1[(size_t)NUSR * HDIM];
__device__ float g_ht0[(size_t)NTXN * HDIM];
__device__ float g_ht1[(size_t)NTXN * HDIM];
__device__ float g_aggu[(size_t)NUSR * HDIM];
__device__ float g_aggt[(size_t)NTXN * HDIM];
__device__ int   g_cntu[NUSR];
__device__ int   g_cntt[NTXN];
__device__ int   g_startu[NUSR];
__device__ int   g_startt[NTXN];
__device__ int   g_tmpu[NUSR];
__device__ int   g_tmpt[NTXN];
__device__ int   g_permu[NEDG];
__device__ int   g_permt[NEDG];
__device__ int   g_cursor[2];
__device__ float4 g_wimg[6 * 2 * 4096];   // [6 (l,t)] x (hi 64KB + lo 64KB)
__device__ float4 g_w1img[2048];          // W1 hi 16KB + lo 16KB

// ===================== CSR build kernels =====================
__global__ void zero_i(int* __restrict__ p, int n) {
    int i = blockIdx.x * blockDim.x + threadIdx.x;
    if (i < n) p[i] = 0;
}

__global__ void count_deg(const int* __restrict__ dst, int* __restrict__ cnt, int n) {
    int i = blockIdx.x * blockDim.x + threadIdx.x;
    if (i < n) atomicAdd(&cnt[__ldg(dst + i)], 1);
}

__global__ void assign_off(const int* __restrict__ cnt, int* __restrict__ start,
                           int* __restrict__ tmp, int* cursor, int n) {
    __shared__ int wsum[8];
    __shared__ int sbase;
    int i = blockIdx.x * 256 + threadIdx.x;
    int lane = threadIdx.x & 31, w = threadIdx.x >> 5;
    int c = (i < n) ? __ldg(cnt + i) : 0;
    int pre = c;
    #pragma unroll
    for (int o = 1; o < 32; o <<= 1) {
        int u = __shfl_up_sync(0xffffffffu, pre, o);
        if (lane >= o) pre += u;
    }
    if (lane == 31) wsum[w] = pre;
    __syncthreads();
    if (threadIdx.x == 0) {
        int s = 0;
        #pragma unroll
        for (int j = 0; j < 8; j++) { int t = wsum[j]; wsum[j] = s; s += t; }
        sbase = atomicAdd(cursor, s);
    }
    __syncthreads();
    int off = sbase + wsum[w] + pre - c;
    if (i < n) { start[i] = off; tmp[i] = off; }
}

__global__ void fill_perm(const int* __restrict__ src, const int* __restrict__ dst,
                          int* __restrict__ tmp, int* __restrict__ perm, int n) {
    int i = blockIdx.x * blockDim.x + threadIdx.x;
    if (i < n) {
        int d = __ldg(dst + i);
        int slot = atomicAdd(&tmp[d], 1);
        perm[slot] = __ldg(src + i);
    }
}

// warp per dst node: agg[d,:] = mean over CSR neighbors of feat[srcidx? idx[src] : src, :]
__global__ void agg_mean(const int* __restrict__ start, const int* __restrict__ cnt,
                         const int* __restrict__ perm,
                         const float* __restrict__ feat, const int* __restrict__ srcidx,
                         float* __restrict__ agg, int n) {
    int t = blockIdx.x * blockDim.x + threadIdx.x;
    int d = t >> 5, lane = t & 31;
    if (d >= n) return;
    int s = __ldg(start + d), c = __ldg(cnt + d);
    float4 acc = make_float4(0.f, 0.f, 0.f, 0.f);
    for (int j = 0; j < c; j++) {
        int src = __ldg(perm + s + j);
        if (srcidx) src = __ldg(srcidx + src);
        float4 v = __ldg((const float4*)(feat + (size_t)src * HDIM) + lane);
        acc.x += v.x; acc.y += v.y; acc.z += v.z; acc.w += v.w;
    }
    float sc = 1.f / (float)(c > 1 ? c : 1);
    acc.x *= sc; acc.y *= sc; acc.z *= sc; acc.w *= sc;
    ((float4*)(agg + (size_t)d * HDIM))[lane] = acc;
}

// ===================== weight prep =====================
__global__ void wprep(const float* __restrict__ Wl, const float* __restrict__ Wr) {
    int lt = blockIdx.x;
    const float* wl = Wl + (size_t)lt * HDIM * HDIM;
    const float* wr = Wr + (size_t)lt * HDIM * HDIM;
    unsigned char* dhi = (unsigned char*)g_wimg + (size_t)lt * 131072;
    unsigned char* dlo = dhi + 65536;
    for (int e = threadIdx.x; e < 256 * 128; e += blockDim.x) {
        int k = e >> 7, n = e & 127;
        float v = (k < 128) ? __ldg(wl + k * HDIM + n) : __ldg(wr + (k - 128) * HDIM + n);
        __nv_bfloat16 hi = __float2bfloat16_rn(v);
        __nv_bfloat16 lo = __float2bfloat16_rn(v - __bfloat162float(hi));
        uint32_t off = (uint32_t)n * 512 + (((uint32_t)k * 2) ^ (uint32_t)((n & 7) * 16));
        *(__nv_bfloat16*)(dhi + off) = hi;
        *(__nv_bfloat16*)(dlo + off) = lo;
    }
}
__global__ void w1prep(const float* __restrict__ W1) {
    unsigned char* dhi = (unsigned char*)g_w1img;
    unsigned char* dlo = dhi + 16384;
    for (int e = blockIdx.x * blockDim.x + threadIdx.x; e < 128 * 64; e += gridDim.x * blockDim.x) {
        int k = e >> 6, n = e & 63;
        float v = __ldg(W1 + k * HID2 + n);
        __nv_bfloat16 hi = __float2bfloat16_rn(v);
        __nv_bfloat16 lo = __float2bfloat16_rn(v - __bfloat162float(hi));
        uint32_t off = (uint32_t)n * 256 + (((uint32_t)k * 2) ^ (uint32_t)((n & 7) * 16));
        *(__nv_bfloat16*)(dhi + off) = hi;
        *(__nv_bfloat16*)(dlo + off) = lo;
    }
}

// ===================== tensor-core fused dual GEMM + bias + BN + ReLU =====================
// out[m,:] = relu(BN( A1[m,:] @ Wl + self[selfidx? idx[m] : m, :] @ Wr + bias ))
// out buffers distinct from inputs (double-buffered); M-tile 128 rows/CTA, K=256, N=128.
#define SMB_SCL 0
#define SMB_SFT 512
#define SMB_BHI 1024
#define SMB_BLO (1024 + 65536)
#define SMB_TOT (1024 + 131072)

__global__ __launch_bounds__(256, 1) void gemm_mma(
    const float* __restrict__ A1,
    const float* __restrict__ self, const int* __restrict__ selfidx,
    const float4* __restrict__ wimg,
    const float* __restrict__ bias,
    const float* __restrict__ gma, const float* __restrict__ bta,
    const float* __restrict__ mu,  const float* __restrict__ var,
    float* __restrict__ out, int M)
{
    extern __shared__ char smem[];
    uint32_t sb = smem_to_u32(smem);
    const int tid  = threadIdx.x;
    const int lane = tid & 31;
    const int wid  = tid >> 5;

    {
        float4* bs = (float4*)(smem + SMB_BHI);
        #pragma unroll 4
        for (int i = tid; i < 8192; i += 256) bs[i] = __ldg(wimg + i);
    }
    if (tid < HDIM) {
        float rs = rsqrtf(__ldg(var + tid) + EPSV) * __ldg(gma + tid);
        ((float*)(smem + SMB_SCL))[tid] = rs;
        ((float*)(smem + SMB_SFT))[tid] = __ldg(bta + tid) + (__ldg(bias + tid) - __ldg(mu + tid)) * rs;
    }
    __syncthreads();

    const int warp_m = wid & 3;
    const int warp_n = wid >> 2;
    const int m0 = blockIdx.x * 128 + warp_m * 32;
    const int n0 = warp_n * 64;
    const int g  = lane >> 2;
    const int tg = lane & 3;

    const float* pa1[4];
    const float* pa2[4];
    int rows[4] = { m0 + g, m0 + g + 8, m0 + g + 16, m0 + g + 24 };
    #pragma unroll
    for (int i = 0; i < 4; i++) {
        int r = rows[i] < M ? rows[i] : (M - 1);
        pa1[i] = A1 + (size_t)r * HDIM;
        int sr = selfidx ? __ldg(selfidx + r) : r;
        pa2[i] = self + (size_t)sr * HDIM;
    }

    const int n_off  = (lane & 7) + ((lane >> 4) << 3);
    const int k_half = (lane & 8) << 1;
    const uint32_t xorv = (uint32_t)((n_off & 7) << 4);
    uint32_t brow_hi[4], brow_lo[4];
    #pragma unroll
    for (int np = 0; np < 4; np++) {
        uint32_t nrow = (uint32_t)(n0 + np * 16 + n_off) * 512u;
        brow_hi[np] = sb + SMB_BHI + nrow;
        brow_lo[np] = sb + SMB_BLO + nrow;
    }

    float acc[2][8][4];
    #pragma unroll
    for (int mt = 0; mt < 2; mt++)
        #pragma unroll
        for (int nt = 0; nt < 8; nt++)
            #pragma unroll
            for (int q = 0; q < 4; q++) acc[mt][nt][q] = 0.f;

    #pragma unroll 2
    for (int kk = 0; kk < 16; kk++) {
        float2 x[4][2];
        if (kk < 8) {
            int k0 = kk * 16 + tg * 2;
            #pragma unroll
            for (int i = 0; i < 4; i++) {
                x[i][0] = *(const float2*)(pa1[i] + k0);
                x[i][1] = *(const float2*)(pa1[i] + k0 + 8);
            }
        } else {
            int k0 = (kk - 8) * 16 + tg * 2;
            #pragma unroll
            for (int i = 0; i < 4; i++) {
                x[i][0] = *(const float2*)(pa2[i] + k0);
                x[i][1] = *(const float2*)(pa2[i] + k0 + 8);
            }
        }
        uint32_t ah[2][4], al[2][4];
        #pragma unroll
        for (int mt = 0; mt < 2; mt++) {
            int i0 = mt * 2, i1 = mt * 2 + 1;
            split2(x[i0][0].x, x[i0][0].y, ah[mt][0], al[mt][0]);
            split2(x[i1][0].x, x[i1][0].y, ah[mt][1], al[mt][1]);
            split2(x[i0][1].x, x[i0][1].y, ah[mt][2], al[mt][2]);
            split2(x[i1][1].x, x[i1][1].y, ah[mt][3], al[mt][3]);
        }

        uint32_t kterm = (uint32_t)((kk * 32 + k_half)) ^ xorv;
        #pragma unroll
        for (int np = 0; np < 4; np++) {
            uint32_t bh0, bh1, bh2, bh3, bl0, bl1, bl2, bl3;
            LDSM_X4(bh0, bh1, bh2, bh3, brow_hi[np] + kterm);
            LDSM_X4(bl0, bl1, bl2, bl3, brow_lo[np] + kterm);
            #pragma unroll
            for (int mt = 0; mt < 2; mt++) {
                MMA_BF16(acc[mt][2 * np],     ah[mt], bh0, bh1);
                MMA_BF16(acc[mt][2 * np],     al[mt], bh0, bh1);
                MMA_BF16(acc[mt][2 * np],     ah[mt], bl0, bl1);
                MMA_BF16(acc[mt][2 * np + 1], ah[mt], bh2, bh3);
                MMA_BF16(acc[mt][2 * np + 1], al[mt], bh2, bh3);
                MMA_BF16(acc[mt][2 * np + 1], ah[mt], bl2, bl3);
            }
        }
    }

    // out buffers are distinct from all inputs (double-buffered) — no pre-store sync
    const float* scl = (const float*)(smem + SMB_SCL);
    const float* sft = (const float*)(smem + SMB_SFT);
    #pragma unroll
    for (int mt = 0; mt < 2; mt++) {
        int r_lo = m0 + mt * 16 + g;
        int r_hi = r_lo + 8;
        #pragma unroll
        for (int nt = 0; nt < 8; nt++) {
            int c = n0 + nt * 8 + tg * 2;
            float s0 = scl[c], s1 = scl[c + 1];
            float f0 = sft[c], f1 = sft[c + 1];
            if (r_lo < M) {
                float2 o;
                o.x = fmaxf(fmaf(acc[mt][nt][0], s0, f0), 0.f);
                o.y = fmaxf(fmaf(acc[mt][nt][1], s1, f1), 0.f);
                *(float2*)(out + (size_t)r_lo * HDIM + c) = o;
            }
            if (r_hi < M) {
                float2 o;
                o.x = fmaxf(fmaf(acc[mt][nt][2], s0, f0), 0.f);
                o.y = fmaxf(fmaf(acc[mt][nt][3], s1, f1), 0.f);
                *(float2*)(out + (size_t)r_hi * HDIM + c) = o;
            }
        }
    }
}

// ===================== tensor-core MLP head =====================
__global__ __launch_bounds__(256, 2) void mlp_mma(
    const float* __restrict__ hu, const float* __restrict__ ht,
    const float4* __restrict__ w1img,
    const float* __restrict__ b1, const float* __restrict__ W2, const float* __restrict__ b2,
    float* __restrict__ out)
{
    __shared__ float4 sB[2048];
    __shared__ float sb1[HID2];
    __shared__ float sW2[HID2 * OUTD];
    __shared__ float sb2[OUTD];
    for (int i = threadIdx.x; i < 2048; i += 256) sB[i] = __ldg(w1img + i);
    if (threadIdx.x < HID2) sb1[threadIdx.x] = __ldg(b1 + threadIdx.x);
    if (threadIdx.x < HID2 * OUTD) sW2[threadIdx.x] = __ldg(W2 + threadIdx.x);
    if (threadIdx.x < OUTD) sb2[threadIdx.x] = __ldg(b2 + threadIdx.x);
    __syncthreads();

    const int lane = threadIdx.x & 31;
    const int wid  = threadIdx.x >> 5;
    const int m0 = blockIdx.x * 256 + wid * 32;
    const int g  = lane >> 2;
    const int tg = lane & 3;

    const float* pa[4];
    int rows[4] = { m0 + g, m0 + g + 8, m0 + g + 16, m0 + g + 24 };
    #pragma unroll
    for (int i = 0; i < 4; i++) {
        int r = rows[i] < NTOT ? rows[i] : (NTOT - 1);
        pa[i] = (r < NUSR) ? hu + (size_t)r * HDIM : ht + (size_t)(r - NUSR) * HDIM;
    }

    const int n_off  = (lane & 7) + ((lane >> 4) << 3);
    const int k_half = (lane & 8) << 1;
    const uint32_t xorv = (uint32_t)((n_off & 7) << 4);
    uint32_t sbu = smem_to_u32(sB);
    uint32_t brow_hi[4], brow_lo[4];
    #pragma unroll
    for (int np = 0; np < 4; np++) {
        uint32_t nrow = (uint32_t)(np * 16 + n_off) * 256u;
        brow_hi[np] = sbu + nrow;
        brow_lo[np] = sbu + 16384u + nrow;
    }

    float acc[2][8][4];
    #pragma unroll
    for (int mt = 0; mt < 2; mt++)
        #pragma unroll
        for (int nt = 0; nt < 8; nt++)
            #pragma unroll
            for (int q = 0; q < 4; q++) acc[mt][nt][q] = 0.f;

    #pragma unroll 2
    for (int kk = 0; kk < 8; kk++) {
        int k0 = kk * 16 + tg * 2;
        float2 x[4][2];
        #pragma unroll
        for (int i = 0; i < 4; i++) {
            x[i][0] = *(const float2*)(pa[i] + k0);
            x[i][1] = *(const float2*)(pa[i] + k0 + 8);
        }
        uint32_t ah[2][4], al[2][4];
        #pragma unroll
        for (int mt = 0; mt < 2; mt++) {
            int i0 = mt * 2, i1 = mt * 2 + 1;
            split2(x[i0][0].x, x[i0][0].y, ah[mt][0], al[mt][0]);
            split2(x[i1][0].x, x[i1][0].y, ah[mt][1], al[mt][1]);
            split2(x[i0][1].x, x[i0][1].y, ah[mt][2], al[mt][2]);
            split2(x[i1][1].x, x[i1][1].y, ah[mt][3], al[mt][3]);
        }
        uint32_t kterm = (uint32_t)((kk * 32 + k_half)) ^ xorv;
        #pragma unroll
        for (int np = 0; np < 4; np++) {
            uint32_t bh0, bh1, bh2, bh3, bl0, bl1, bl2, bl3;
            LDSM_X4(bh0, bh1, bh2, bh3, brow_hi[np] + kterm);
            LDSM_X4(bl0, bl1, bl2, bl3, brow_lo[np] + kterm);
            #pragma unroll
            for (int mt = 0; mt < 2; mt++) {
                MMA_BF16(acc[mt][2 * np],     ah[mt], bh0, bh1);
                MMA_BF16(acc[mt][2 * np],     al[mt], bh0, bh1);
                MMA_BF16(acc[mt][2 * np],     ah[mt], bl0, bl1);
                MMA_BF16(acc[mt][2 * np + 1], ah[mt], bh2, bh3);
                MMA_BF16(acc[mt][2 * np + 1], al[mt], bh2, bh3);
                MMA_BF16(acc[mt][2 * np + 1], ah[mt], bl2, bl3);
            }
        }
    }

    #pragma unroll
    for (int mt = 0; mt < 2; mt++) {
        #pragma unroll
        for (int half = 0; half < 2; half++) {
            int row = m0 + mt * 16 + g + half * 8;
            float oA = 0.f, oB = 0.f;
            #pragma unroll
            for (int nt = 0; nt < 8; nt++) {
                int c = nt * 8 + tg * 2;
                float h0 = fmaxf(acc[mt][nt][half * 2 + 0] + sb1[c],     0.f);
                float h1 = fmaxf(acc[mt][nt][half * 2 + 1] + sb1[c + 1], 0.f);
                oA = fmaf(h0, sW2[c * OUTD],     fmaf(h1, sW2[(c + 1) * OUTD],     oA));
                oB = fmaf(h0, sW2[c * OUTD + 1], fmaf(h1, sW2[(c + 1) * OUTD + 1], oB));
            }
            oA += __shfl_xor_sync(0xffffffffu, oA, 1);
            oA += __shfl_xor_sync(0xffffffffu, oA, 2);
            oB += __shfl_xor_sync(0xffffffffu, oB, 1);
            oB += __shfl_xor_sync(0xffffffffu, oB, 2);
            if (tg == 0 && row < NTOT) {
                out[(size_t)row * OUTD + 0] = oA + sb2[0];
                out[(size_t)row * OUTD + 1] = oB + sb2[1];
            }
        }
    }
}

// ===================== launcher =====================
extern "C" void kernel_launch(void* const* d_in, const int* in_sizes, int n_in,
                              void* d_out, int out_size) {
    (void)in_sizes; (void)n_in; (void)out_size;
    const int*   x_user  = (const int*)  d_in[0];
    const int*   x_txn   = (const int*)  d_in[1];
    const int*   ei0_src = (const int*)  d_in[2];
    const int*   ei0_dst = (const int*)  d_in[3];
    const int*   ei1_src = (const int*)  d_in[4];
    const int*   ei1_dst = (const int*)  d_in[5];
    const float* emb_u   = (const float*)d_in[6];
    const float* emb_t   = (const float*)d_in[7];
    const float* Wl      = (const float*)d_in[8];
    const float* bl      = (const float*)d_in[9];
    const float* Wr      = (const float*)d_in[10];
    const float* bn_g    = (const float*)d_in[11];
    const float* bn_b    = (const float*)d_in[12];
    const float* bn_m    = (const float*)d_in[13];
    const float* bn_v    = (const float*)d_in[14];
    const float* W1      = (const float*)d_in[15];
    const float* b1      = (const float*)d_in[16];
    const float* W2      = (const float*)d_in[17];
    const float* b2      = (const float*)d_in[18];
    float* out = (float*)d_out;

    float *hu[2], *ht[2], *aggu, *aggt;
    int *cntu, *cntt, *startu, *startt, *tmpu, *tmpt, *permu, *permt, *cursor;
    float4 *wimg, *w1img;
    cudaGetSymbolAddress((void**)&hu[0],  g_hu0);
    cudaGetSymbolAddress((void**)&hu[1],  g_hu1);
    cudaGetSymbolAddress((void**)&ht[0],  g_ht0);
    cudaGetSymbolAddress((void**)&ht[1],  g_ht1);
    cudaGetSymbolAddress((void**)&aggu,   g_aggu);
    cudaGetSymbolAddress((void**)&aggt,   g_aggt);
    cudaGetSymbolAddress((void**)&cntu,   g_cntu);
    cudaGetSymbolAddress((void**)&cntt,   g_cntt);
    cudaGetSymbolAddress((void**)&startu, g_startu);
    cudaGetSymbolAddress((void**)&startt, g_startt);
    cudaGetSymbolAddress((void**)&tmpu,   g_tmpu);
    cudaGetSymbolAddress((void**)&tmpt,   g_tmpt);
    cudaGetSymbolAddress((void**)&permu,  g_permu);
    cudaGetSymbolAddress((void**)&permt,  g_permt);
    cudaGetSymbolAddress((void**)&cursor, g_cursor);
    cudaGetSymbolAddress((void**)&wimg,   g_wimg);
    cudaGetSymbolAddress((void**)&w1img,  g_w1img);

    cudaFuncSetAttribute(gemm_mma, cudaFuncAttributeMaxDynamicSharedMemorySize, SMB_TOT);

    // 0) bake weight images
    wprep<<<6, 256>>>(Wl, Wr);
    w1prep<<<8, 256>>>(W1);

    // 1) CSR build (layer-invariant)
    zero_i<<<(NTXN + 255) / 256, 256>>>(cntt, NTXN);
    zero_i<<<(NUSR + 255) / 256, 256>>>(cntu, NUSR);
    zero_i<<<1, 32>>>(cursor, 2);
    count_deg<<<(NEDG + 255) / 256, 256>>>(ei0_dst, cntt, NEDG);
    count_deg<<<(NEDG + 255) / 256, 256>>>(ei1_dst, cntu, NEDG);
    assign_off<<<(NTXN + 255) / 256, 256>>>(cntt, startt, tmpt, cursor + 0, NTXN);
    assign_off<<<(NUSR + 255) / 256, 256>>>(cntu, startu, tmpu, cursor + 1, NUSR);
    fill_perm<<<(NEDG + 255) / 256, 256>>>(ei0_src, ei0_dst, tmpt, permt, NEDG);
    fill_perm<<<(NEDG + 255) / 256, 256>>>(ei1_src, ei1_dst, tmpu, permu, NEDG);

    // 2) layers (double-buffered; layer 0 reads embeddings through index arrays)
    for (int l = 0; l < NLAY; l++) {
        const float* su  = (l == 0) ? emb_u : hu[(l + 1) & 1];
        const float* st_ = (l == 0) ? emb_t : ht[(l + 1) & 1];
        const int* ixu = (l == 0) ? x_user : nullptr;
        const int* ixt = (l == 0) ? x_txn  : nullptr;
        float* out_t = ht[l & 1];
        float* out_u = hu[l & 1];

        // aggregation (parallel CSR gather-mean)
        agg_mean<<<(NTXN * 32 + 255) / 256, 256>>>(startt, cntt, permt, su,  ixu, aggt, NTXN);
        agg_mean<<<(NUSR * 32 + 255) / 256, 256>>>(startu, cntu, permu, st_, ixt, aggu, NUSR);

        // txn nodes: weights/bias (l,0), BN (l,1)
        {
            int lt = l * 2 + 0;
            gemm_mma<<<(NTXN + 127) / 128, 256, SMB_TOT>>>(
                aggt, st_, ixt,
                wimg + (size_t)lt * 8192,
                bl   + (size_t)lt * HDIM,
                bn_g + (size_t)(l * 2 + 1) * HDIM, bn_b + (size_t)(l * 2 + 1) * HDIM,
                bn_m + (size_t)(l * 2 + 1) * HDIM, bn_v + (size_t)(l * 2 + 1) * HDIM,
                out_t, NTXN);
        }
        // user nodes: weights/bias (l,1), BN (l,0)
        {
            int lt = l * 2 + 1;
            gemm_mma<<<(NUSR + 127) / 128, 256, SMB_TOT>>>(
                aggu, su, ixu,
                wimg + (size_t)lt * 8192,
                bl   + (size_t)lt * HDIM,
                bn_g + (size_t)(l * 2 + 0) * HDIM, bn_b + (size_t)(l * 2 + 0) * HDIM,
                bn_m + (size_t)(l * 2 + 0) * HDIM, bn_v + (size_t)(l * 2 + 0) * HDIM,
                out_u, NUSR);
        }
    }

    // 3) MLP head (final layer wrote buffer index (NLAY-1)&1 = 0)
    mlp_mma<<<(NTOT + 255) / 256, 256>>>(hu[(NLAY - 1) & 1], ht[(NLAY - 1) & 1],
                                         w1img, b1, W2, b2, out);
}

// round 14
// speedup vs baseline: 1.2936x; 1.0435x over previous
#include <cuda_runtime.h>
#include <cuda_bf16.h>
#include <cstdint>

#define NUSR 100000
#define NTXN 400000
#define NEDG 400000
#define HDIM 128
#define NLAY 3
#define HID2 64
#define OUTD 2
#define EPSV 1e-5f
#define NTOT (NUSR + NTXN)
#define NSM  148

// ===================== helpers =====================
__device__ __forceinline__ uint32_t smem_to_u32(const void* p) {
    uint32_t a;
    asm("{ .reg .u64 t; cvta.to.shared.u64 t, %1; cvt.u32.u64 %0, t; }" : "=r"(a) : "l"(p));
    return a;
}
__device__ __forceinline__ void split2(float x, float y, uint32_t& hi, uint32_t& lo) {
    __nv_bfloat162 h = __floats2bfloat162_rn(x, y);
    float rx = x - __bfloat162float(h.x);
    float ry = y - __bfloat162float(h.y);
    __nv_bfloat162 l = __floats2bfloat162_rn(rx, ry);
    hi = *(uint32_t*)&h;
    lo = *(uint32_t*)&l;
}
#define LDSM_X4(r0, r1, r2, r3, addr) \
    asm volatile("ldmatrix.sync.aligned.m8n8.x4.shared.b16 {%0,%1,%2,%3}, [%4];" \
                 : "=r"(r0), "=r"(r1), "=r"(r2), "=r"(r3) : "r"(addr))
#define MMA_BF16(d, a, b0, b1) \
    asm volatile("mma.sync.aligned.m16n8k16.row.col.f32.bf16.bf16.f32 " \
                 "{%0,%1,%2,%3}, {%4,%5,%6,%7}, {%8,%9}, {%0,%1,%2,%3};" \
                 : "+f"((d)[0]), "+f"((d)[1]), "+f"((d)[2]), "+f"((d)[3]) \
                 : "r"((a)[0]), "r"((a)[1]), "r"((a)[2]), "r"((a)[3]), "r"(b0), "r"(b1))

// ===================== scratch (device globals) =====================
__device__ float g_hu0[(size_t)NUSR * HDIM];
__device__ float g_hu1[(size_t)NUSR * HDIM];
__device__ float g_ht0[(size_t)NTXN * HDIM];
__device__ float g_ht1[(size_t)NTXN * HDIM];
__device__ float g_aggu[(size_t)NUSR * HDIM];
__device__ float g_aggt[(size_t)NTXN * HDIM];
__device__ int   g_cntu[NUSR];
__device__ int   g_cntt[NTXN];
__device__ int   g_startu[NUSR];
__device__ int   g_startt[NTXN];
__device__ int   g_tmpu[NUSR];
__device__ int   g_tmpt[NTXN];
__device__ int   g_permu[NEDG];
__device__ int   g_permt[NEDG];
__device__ int   g_cursor[2];
__device__ float4 g_wimg[6 * 2 * 4096];   // [6 (l,t)] x (hi 64KB + lo 64KB)
__device__ float4 g_w1img[2048];          // W1 hi 16KB + lo 16KB

// ===================== CSR build kernels =====================
__global__ void zero_i(int* __restrict__ p, int n) {
    int i = blockIdx.x * blockDim.x + threadIdx.x;
    if (i < n) p[i] = 0;
}

__global__ void count_deg(const int* __restrict__ dst, int* __restrict__ cnt, int n) {
    int i = blockIdx.x * blockDim.x + threadIdx.x;
    if (i < n) atomicAdd(&cnt[__ldg(dst + i)], 1);
}

__global__ void assign_off(const int* __restrict__ cnt, int* __restrict__ start,
                           int* __restrict__ tmp, int* cursor, int n) {
    __shared__ int wsum[8];
    __shared__ int sbase;
    int i = blockIdx.x * 256 + threadIdx.x;
    int lane = threadIdx.x & 31, w = threadIdx.x >> 5;
    int c = (i < n) ? __ldg(cnt + i) : 0;
    int pre = c;
    #pragma unroll
    for (int o = 1; o < 32; o <<= 1) {
        int u = __shfl_up_sync(0xffffffffu, pre, o);
        if (lane >= o) pre += u;
    }
    if (lane == 31) wsum[w] = pre;
    __syncthreads();
    if (threadIdx.x == 0) {
        int s = 0;
        #pragma unroll
        for (int j = 0; j < 8; j++) { int t = wsum[j]; wsum[j] = s; s += t; }
        sbase = atomicAdd(cursor, s);
    }
    __syncthreads();
    int off = sbase + wsum[w] + pre - c;
    if (i < n) { start[i] = off; tmp[i] = off; }
}

__global__ void fill_perm(const int* __restrict__ src, const int* __restrict__ dst,
                          int* __restrict__ tmp, int* __restrict__ perm, int n) {
    int i = blockIdx.x * blockDim.x + threadIdx.x;
    if (i < n) {
        int d = __ldg(dst + i);
        int slot = atomicAdd(&tmp[d], 1);
        perm[slot] = __ldg(src + i);
    }
}

// warp per dst node: agg[d,:] = mean over CSR neighbors of feat[srcidx? idx[src] : src, :]
__global__ void agg_mean(const int* __restrict__ start, const int* __restrict__ cnt,
                         const int* __restrict__ perm,
                         const float* __restrict__ feat, const int* __restrict__ srcidx,
                         float* __restrict__ agg, int n) {
    int t = blockIdx.x * blockDim.x + threadIdx.x;
    int d = t >> 5, lane = t & 31;
    if (d >= n) return;
    int s = __ldg(start + d), c = __ldg(cnt + d);
    float4 acc = make_float4(0.f, 0.f, 0.f, 0.f);
    for (int j = 0; j < c; j++) {
        int src = __ldg(perm + s + j);
        if (srcidx) src = __ldg(srcidx + src);
        float4 v = __ldg((const float4*)(feat + (size_t)src * HDIM) + lane);
        acc.x += v.x; acc.y += v.y; acc.z += v.z; acc.w += v.w;
    }
    float sc = 1.f / (float)(c > 1 ? c : 1);
    acc.x *= sc; acc.y *= sc; acc.z *= sc; acc.w *= sc;
    ((float4*)(agg + (size_t)d * HDIM))[lane] = acc;
}

// ===================== weight prep =====================
__global__ void wprep(const float* __restrict__ Wl, const float* __restrict__ Wr) {
    int lt = blockIdx.x;
    const float* wl = Wl + (size_t)lt * HDIM * HDIM;
    const float* wr = Wr + (size_t)lt * HDIM * HDIM;
    unsigned char* dhi = (unsigned char*)g_wimg + (size_t)lt * 131072;
    unsigned char* dlo = dhi + 65536;
    for (int e = threadIdx.x; e < 256 * 128; e += blockDim.x) {
        int k = e >> 7, n = e & 127;
        float v = (k < 128) ? __ldg(wl + k * HDIM + n) : __ldg(wr + (k - 128) * HDIM + n);
        __nv_bfloat16 hi = __float2bfloat16_rn(v);
        __nv_bfloat16 lo = __float2bfloat16_rn(v - __bfloat162float(hi));
        uint32_t off = (uint32_t)n * 512 + (((uint32_t)k * 2) ^ (uint32_t)((n & 7) * 16));
        *(__nv_bfloat16*)(dhi + off) = hi;
        *(__nv_bfloat16*)(dlo + off) = lo;
    }
}
__global__ void w1prep(const float* __restrict__ W1) {
    unsigned char* dhi = (unsigned char*)g_w1img;
    unsigned char* dlo = dhi + 16384;
    for (int e = blockIdx.x * blockDim.x + threadIdx.x; e < 128 * 64; e += gridDim.x * blockDim.x) {
        int k = e >> 6, n = e & 63;
        float v = __ldg(W1 + k * HID2 + n);
        __nv_bfloat16 hi = __float2bfloat16_rn(v);
        __nv_bfloat16 lo = __float2bfloat16_rn(v - __bfloat162float(hi));
        uint32_t off = (uint32_t)n * 256 + (((uint32_t)k * 2) ^ (uint32_t)((n & 7) * 16));
        *(__nv_bfloat16*)(dhi + off) = hi;
        *(__nv_bfloat16*)(dlo + off) = lo;
    }
}

// ===================== persistent tensor-core fused dual GEMM + bias + BN + ReLU ==========
// out[m,:] = relu(BN( A1[m,:] @ Wl + self[selfidx? idx[m] : m, :] @ Wr + bias ))
// Persistent: grid = NSM CTAs, each loops over 128-row tiles. Weights staged once.
// A loads software-pipelined (prefetch kk+1 during kk's MMA chain).
#define SMB_SCL 0
#define SMB_SFT 512
#define SMB_BHI 1024
#define SMB_BLO (1024 + 65536)
#define SMB_TOT (1024 + 131072)

__global__ __launch_bounds__(256, 1) void gemm_mma(
    const float* __restrict__ A1,
    const float* __restrict__ self, const int* __restrict__ selfidx,
    const float4* __restrict__ wimg,
    const float* __restrict__ bias,
    const float* __restrict__ gma, const float* __restrict__ bta,
    const float* __restrict__ mu,  const float* __restrict__ var,
    float* __restrict__ out, int M)
{
    extern __shared__ char smem[];
    uint32_t sb = smem_to_u32(smem);
    const int tid  = threadIdx.x;
    const int lane = tid & 31;
    const int wid  = tid >> 5;

    // ---- one-time staging per CTA ----
    {
        float4* bs = (float4*)(smem + SMB_BHI);
        #pragma unroll 4
        for (int i = tid; i < 8192; i += 256) bs[i] = __ldg(wimg + i);
    }
    if (tid < HDIM) {
        float rs = rsqrtf(__ldg(var + tid) + EPSV) * __ldg(gma + tid);
        ((float*)(smem + SMB_SCL))[tid] = rs;
        ((float*)(smem + SMB_SFT))[tid] = __ldg(bta + tid) + (__ldg(bias + tid) - __ldg(mu + tid)) * rs;
    }
    __syncthreads();

    const int warp_m = wid & 3;
    const int warp_n = wid >> 2;
    const int n0 = warp_n * 64;
    const int g  = lane >> 2;
    const int tg = lane & 3;

    // B ldmatrix addresses (fixed across tiles)
    const int n_off  = (lane & 7) + ((lane >> 4) << 3);
    const int k_half = (lane & 8) << 1;
    const uint32_t xorv = (uint32_t)((n_off & 7) << 4);
    uint32_t brow_hi[4], brow_lo[4];
    #pragma unroll
    for (int np = 0; np < 4; np++) {
        uint32_t nrow = (uint32_t)(n0 + np * 16 + n_off) * 512u;
        brow_hi[np] = sb + SMB_BHI + nrow;
        brow_lo[np] = sb + SMB_BLO + nrow;
    }
    const float* scl = (const float*)(smem + SMB_SCL);
    const float* sft = (const float*)(smem + SMB_SFT);

    const int ntiles = (M + 127) >> 7;
    for (int tile = blockIdx.x; tile < ntiles; tile += gridDim.x) {
        const int m0 = tile * 128 + warp_m * 32;

        // A row pointers (clamped; stores guarded)
        const float* pa1[4];
        const float* pa2[4];
        #pragma unroll
        for (int i = 0; i < 4; i++) {
            int r = m0 + g + i * 8;
            r = r < M ? r : (M - 1);
            pa1[i] = A1 + (size_t)r * HDIM;
            int sr = selfidx ? __ldg(selfidx + r) : r;
            pa2[i] = self + (size_t)sr * HDIM;
        }

        float acc[2][8][4];
        #pragma unroll
        for (int mt = 0; mt < 2; mt++)
            #pragma unroll
            for (int nt = 0; nt < 8; nt++)
                #pragma unroll
                for (int q = 0; q < 4; q++) acc[mt][nt][q] = 0.f;

        // ---- software-pipelined k-loop ----
        float2 xc[4][2];
        {
            int k0 = tg * 2;
            #pragma unroll
            for (int i = 0; i < 4; i++) {
                xc[i][0] = *(const float2*)(pa1[i] + k0);
                xc[i][1] = *(const float2*)(pa1[i] + k0 + 8);
            }
        }
        #pragma unroll 2
        for (int kk = 0; kk < 16; kk++) {
            // split current block
            uint32_t ah[2][4], al[2][4];
            #pragma unroll
            for (int mt = 0; mt < 2; mt++) {
                int i0 = mt * 2, i1 = mt * 2 + 1;
                split2(xc[i0][0].x, xc[i0][0].y, ah[mt][0], al[mt][0]);
                split2(xc[i1][0].x, xc[i1][0].y, ah[mt][1], al[mt][1]);
                split2(xc[i0][1].x, xc[i0][1].y, ah[mt][2], al[mt][2]);
                split2(xc[i1][1].x, xc[i1][1].y, ah[mt][3], al[mt][3]);
            }
            // prefetch next block (A1 for kn<8, A2 for kn>=8)
            float2 xn[4][2];
            if (kk < 15) {
                int kn = kk + 1;
                int k0 = (kn & 7) * 16 + tg * 2;
                if (kn < 8) {
                    #pragma unroll
                    for (int i = 0; i < 4; i++) {
                        xn[i][0] = *(const float2*)(pa1[i] + k0);
                        xn[i][1] = *(const float2*)(pa1[i] + k0 + 8);
                    }
                } else {
                    #pragma unroll
                    for (int i = 0; i < 4; i++) {
                        xn[i][0] = *(const float2*)(pa2[i] + k0);
                        xn[i][1] = *(const float2*)(pa2[i] + k0 + 8);
                    }
                }
            }
            // B fragments + 3-chain MMA
            uint32_t kterm = (uint32_t)((kk * 32 + k_half)) ^ xorv;
            #pragma unroll
            for (int np = 0; np < 4; np++) {
                uint32_t bh0, bh1, bh2, bh3, bl0, bl1, bl2, bl3;
                LDSM_X4(bh0, bh1, bh2, bh3, brow_hi[np] + kterm);
                LDSM_X4(bl0, bl1, bl2, bl3, brow_lo[np] + kterm);
                #pragma unroll
                for (int mt = 0; mt < 2; mt++) {
                    MMA_BF16(acc[mt][2 * np],     ah[mt], bh0, bh1);
                    MMA_BF16(acc[mt][2 * np],     al[mt], bh0, bh1);
                    MMA_BF16(acc[mt][2 * np],     ah[mt], bl0, bl1);
                    MMA_BF16(acc[mt][2 * np + 1], ah[mt], bh2, bh3);
                    MMA_BF16(acc[mt][2 * np + 1], al[mt], bh2, bh3);
                    MMA_BF16(acc[mt][2 * np + 1], ah[mt], bl2, bl3);
                }
            }
            if (kk < 15) {
                #pragma unroll
                for (int i = 0; i < 4; i++) { xc[i][0] = xn[i][0]; xc[i][1] = xn[i][1]; }
            }
        }

        // ---- epilogue (out distinct from inputs; no sync needed) ----
        #pragma unroll
        for (int mt = 0; mt < 2; mt++) {
            int r_lo = m0 + mt * 16 + g;
            int r_hi = r_lo + 8;
            #pragma unroll
            for (int nt = 0; nt < 8; nt++) {
                int c = n0 + nt * 8 + tg * 2;
                float s0 = scl[c], s1 = scl[c + 1];
                float f0 = sft[c], f1 = sft[c + 1];
                if (r_lo < M) {
                    float2 o;
                    o.x = fmaxf(fmaf(acc[mt][nt][0], s0, f0), 0.f);
                    o.y = fmaxf(fmaf(acc[mt][nt][1], s1, f1), 0.f);
                    *(float2*)(out + (size_t)r_lo * HDIM + c) = o;
                }
                if (r_hi < M) {
                    float2 o;
                    o.x = fmaxf(fmaf(acc[mt][nt][2], s0, f0), 0.f);
                    o.y = fmaxf(fmaf(acc[mt][nt][3], s1, f1), 0.f);
                    *(float2*)(out + (size_t)r_hi * HDIM + c) = o;
                }
            }
        }
    }
}

// ===================== tensor-core MLP head =====================
__global__ __launch_bounds__(256, 2) void mlp_mma(
    const float* __restrict__ hu, const float* __restrict__ ht,
    const float4* __restrict__ w1img,
    const float* __restrict__ b1, const float* __restrict__ W2, const float* __restrict__ b2,
    float* __restrict__ out)
{
    __shared__ float4 sB[2048];
    __shared__ float sb1[HID2];
    __shared__ float sW2[HID2 * OUTD];
    __shared__ float sb2[OUTD];
    for (int i = threadIdx.x; i < 2048; i += 256) sB[i] = __ldg(w1img + i);
    if (threadIdx.x < HID2) sb1[threadIdx.x] = __ldg(b1 + threadIdx.x);
    if (threadIdx.x < HID2 * OUTD) sW2[threadIdx.x] = __ldg(W2 + threadIdx.x);
    if (threadIdx.x < OUTD) sb2[threadIdx.x] = __ldg(b2 + threadIdx.x);
    __syncthreads();

    const int lane = threadIdx.x & 31;
    const int wid  = threadIdx.x >> 5;
    const int m0 = blockIdx.x * 256 + wid * 32;
    const int g  = lane >> 2;
    const int tg = lane & 3;

    const float* pa[4];
    int rows[4] = { m0 + g, m0 + g + 8, m0 + g + 16, m0 + g + 24 };
    #pragma unroll
    for (int i = 0; i < 4; i++) {
        int r = rows[i] < NTOT ? rows[i] : (NTOT - 1);
        pa[i] = (r < NUSR) ? hu + (size_t)r * HDIM : ht + (size_t)(r - NUSR) * HDIM;
    }

    const int n_off  = (lane & 7) + ((lane >> 4) << 3);
    const int k_half = (lane & 8) << 1;
    const uint32_t xorv = (uint32_t)((n_off & 7) << 4);
    uint32_t sbu = smem_to_u32(sB);
    uint32_t brow_hi[4], brow_lo[4];
    #pragma unroll
    for (int np = 0; np < 4; np++) {
        uint32_t nrow = (uint32_t)(np * 16 + n_off) * 256u;
        brow_hi[np] = sbu + nrow;
        brow_lo[np] = sbu + 16384u + nrow;
    }

    float acc[2][8][4];
    #pragma unroll
    for (int mt = 0; mt < 2; mt++)
        #pragma unroll
        for (int nt = 0; nt < 8; nt++)
            #pragma unroll
            for (int q = 0; q < 4; q++) acc[mt][nt][q] = 0.f;

    #pragma unroll 2
    for (int kk = 0; kk < 8; kk++) {
        int k0 = kk * 16 + tg * 2;
        float2 x[4][2];
        #pragma unroll
        for (int i = 0; i < 4; i++) {
            x[i][0] = *(const float2*)(pa[i] + k0);
            x[i][1] = *(const float2*)(pa[i] + k0 + 8);
        }
        uint32_t ah[2][4], al[2][4];
        #pragma unroll
        for (int mt = 0; mt < 2; mt++) {
            int i0 = mt * 2, i1 = mt * 2 + 1;
            split2(x[i0][0].x, x[i0][0].y, ah[mt][0], al[mt][0]);
            split2(x[i1][0].x, x[i1][0].y, ah[mt][1], al[mt][1]);
            split2(x[i0][1].x, x[i0][1].y, ah[mt][2], al[mt][2]);
            split2(x[i1][1].x, x[i1][1].y, ah[mt][3], al[mt][3]);
        }
        uint32_t kterm = (uint32_t)((kk * 32 + k_half)) ^ xorv;
        #pragma unroll
        for (int np = 0; np < 4; np++) {
            uint32_t bh0, bh1, bh2, bh3, bl0, bl1, bl2, bl3;
            LDSM_X4(bh0, bh1, bh2, bh3, brow_hi[np] + kterm);
            LDSM_X4(bl0, bl1, bl2, bl3, brow_lo[np] + kterm);
            #pragma unroll
            for (int mt = 0; mt < 2; mt++) {
                MMA_BF16(acc[mt][2 * np],     ah[mt], bh0, bh1);
                MMA_BF16(acc[mt][2 * np],     al[mt], bh0, bh1);
                MMA_BF16(acc[mt][2 * np],     ah[mt], bl0, bl1);
                MMA_BF16(acc[mt][2 * np + 1], ah[mt], bh2, bh3);
                MMA_BF16(acc[mt][2 * np + 1], al[mt], bh2, bh3);
                MMA_BF16(acc[mt][2 * np + 1], ah[mt], bl2, bl3);
            }
        }
    }

    #pragma unroll
    for (int mt = 0; mt < 2; mt++) {
        #pragma unroll
        for (int half = 0; half < 2; half++) {
            int row = m0 + mt * 16 + g + half * 8;
            float oA = 0.f, oB = 0.f;
            #pragma unroll
            for (int nt = 0; nt < 8; nt++) {
                int c = nt * 8 + tg * 2;
                float h0 = fmaxf(acc[mt][nt][half * 2 + 0] + sb1[c],     0.f);
                float h1 = fmaxf(acc[mt][nt][half * 2 + 1] + sb1[c + 1], 0.f);
                oA = fmaf(h0, sW2[c * OUTD],     fmaf(h1, sW2[(c + 1) * OUTD],     oA));
                oB = fmaf(h0, sW2[c * OUTD + 1], fmaf(h1, sW2[(c + 1) * OUTD + 1], oB));
            }
            oA += __shfl_xor_sync(0xffffffffu, oA, 1);
            oA += __shfl_xor_sync(0xffffffffu, oA, 2);
            oB += __shfl_xor_sync(0xffffffffu, oB, 1);
            oB += __shfl_xor_sync(0xffffffffu, oB, 2);
            if (tg == 0 && row < NTOT) {
                out[(size_t)row * OUTD + 0] = oA + sb2[0];
                out[(size_t)row * OUTD + 1] = oB + sb2[1];
            }
        }
    }
}

// ===================== launcher =====================
extern "C" void kernel_launch(void* const* d_in, const int* in_sizes, int n_in,
                              void* d_out, int out_size) {
    (void)in_sizes; (void)n_in; (void)out_size;
    const int*   x_user  = (const int*)  d_in[0];
    const int*   x_txn   = (const int*)  d_in[1];
    const int*   ei0_src = (const int*)  d_in[2];
    const int*   ei0_dst = (const int*)  d_in[3];
    const int*   ei1_src = (const int*)  d_in[4];
    const int*   ei1_dst = (const int*)  d_in[5];
    const float* emb_u   = (const float*)d_in[6];
    const float* emb_t   = (const float*)d_in[7];
    const float* Wl      = (const float*)d_in[8];
    const float* bl      = (const float*)d_in[9];
    const float* Wr      = (const float*)d_in[10];
    const float* bn_g    = (const float*)d_in[11];
    const float* bn_b    = (const float*)d_in[12];
    const float* bn_m    = (const float*)d_in[13];
    const float* bn_v    = (const float*)d_in[14];
    const float* W1      = (const float*)d_in[15];
    const float* b1      = (const float*)d_in[16];
    const float* W2      = (const float*)d_in[17];
    const float* b2      = (const float*)d_in[18];
    float* out = (float*)d_out;

    float *hu[2], *ht[2], *aggu, *aggt;
    int *cntu, *cntt, *startu, *startt, *tmpu, *tmpt, *permu, *permt, *cursor;
    float4 *wimg, *w1img;
    cudaGetSymbolAddress((void**)&hu[0],  g_hu0);
    cudaGetSymbolAddress((void**)&hu[1],  g_hu1);
    cudaGetSymbolAddress((void**)&ht[0],  g_ht0);
    cudaGetSymbolAddress((void**)&ht[1],  g_ht1);
    cudaGetSymbolAddress((void**)&aggu,   g_aggu);
    cudaGetSymbolAddress((void**)&aggt,   g_aggt);
    cudaGetSymbolAddress((void**)&cntu,   g_cntu);
    cudaGetSymbolAddress((void**)&cntt,   g_cntt);
    cudaGetSymbolAddress((void**)&startu, g_startu);
    cudaGetSymbolAddress((void**)&startt, g_startt);
    cudaGetSymbolAddress((void**)&tmpu,   g_tmpu);
    cudaGetSymbolAddress((void**)&tmpt,   g_tmpt);
    cudaGetSymbolAddress((void**)&permu,  g_permu);
    cudaGetSymbolAddress((void**)&permt,  g_permt);
    cudaGetSymbolAddress((void**)&cursor, g_cursor);
    cudaGetSymbolAddress((void**)&wimg,   g_wimg);
    cudaGetSymbolAddress((void**)&w1img,  g_w1img);

    cudaFuncSetAttribute(gemm_mma, cudaFuncAttributeMaxDynamicSharedMemorySize, SMB_TOT);

    // 0) bake weight images
    wprep<<<6, 256>>>(Wl, Wr);
    w1prep<<<8, 256>>>(W1);

    // 1) CSR build (layer-invariant)
    zero_i<<<(NTXN + 255) / 256, 256>>>(cntt, NTXN);
    zero_i<<<(NUSR + 255) / 256, 256>>>(cntu, NUSR);
    zero_i<<<1, 32>>>(cursor, 2);
    count_deg<<<(NEDG + 255) / 256, 256>>>(ei0_dst, cntt, NEDG);
    count_deg<<<(NEDG + 255) / 256, 256>>>(ei1_dst, cntu, NEDG);
    assign_off<<<(NTXN + 255) / 256, 256>>>(cntt, startt, tmpt, cursor + 0, NTXN);
    assign_off<<<(NUSR + 255) / 256, 256>>>(cntu, startu, tmpu, cursor + 1, NUSR);
    fill_perm<<<(NEDG + 255) / 256, 256>>>(ei0_src, ei0_dst, tmpt, permt, NEDG);
    fill_perm<<<(NEDG + 255) / 256, 256>>>(ei1_src, ei1_dst, tmpu, permu, NEDG);

    // 2) layers (double-buffered; layer 0 reads embeddings through index arrays)
    for (int l = 0; l < NLAY; l++) {
        const float* su  = (l == 0) ? emb_u : hu[(l + 1) & 1];
        const float* st_ = (l == 0) ? emb_t : ht[(l + 1) & 1];
        const int* ixu = (l == 0) ? x_user : nullptr;
        const int* ixt = (l == 0) ? x_txn  : nullptr;
        float* out_t = ht[l & 1];
        float* out_u = hu[l & 1];

        agg_mean<<<(NTXN * 32 + 255) / 256, 256>>>(startt, cntt, permt, su,  ixu, aggt, NTXN);
        agg_mean<<<(NUSR * 32 + 255) / 256, 256>>>(startu, cntu, permu, st_, ixt, aggu, NUSR);

        // txn nodes: weights/bias (l,0), BN (l,1) — persistent grid
        {
            int lt = l * 2 + 0;
            gemm_mma<<<NSM, 256, SMB_TOT>>>(
                aggt, st_, ixt,
                wimg + (size_t)lt * 8192,
                bl   + (size_t)lt * HDIM,
                bn_g + (size_t)(l * 2 + 1) * HDIM, bn_b + (size_t)(l * 2 + 1) * HDIM,
                bn_m + (size_t)(l * 2 + 1) * HDIM, bn_v + (size_t)(l * 2 + 1) * HDIM,
                out_t, NTXN);
        }
        // user nodes: weights/bias (l,1), BN (l,0) — persistent grid
        {
            int lt = l * 2 + 1;
            gemm_mma<<<NSM, 256, SMB_TOT>>>(
                aggu, su, ixu,
                wimg + (size_t)lt * 8192,
                bl   + (size_t)lt * HDIM,
                bn_g + (size_t)(l * 2 + 0) * HDIM, bn_b + (size_t)(l * 2 + 0) * HDIM,
                bn_m + (size_t)(l * 2 + 0) * HDIM, bn_v + (size_t)(l * 2 + 0) * HDIM,
                out_u, NUSR);
        }
    }

    // 3) MLP head (final layer wrote buffer index (NLAY-1)&1 = 0)
    mlp_mma<<<(NTOT + 255) / 256, 256>>>(hu[(NLAY - 1) & 1], ht[(NLAY - 1) & 1],
                                         w1img, b1, W2, b2, out);
}